// round 1
// baseline (speedup 1.0000x reference)
#include <cuda_runtime.h>

// Problem dims (fixed by the dataset)
#define BATCH 32
#define TT    1024
#define DD    512
#define HH    512
#define OO    256
#define MTOT  (BATCH * TT)   // 32768

// Scratch: __device__ globals (no allocation allowed).
// g_I0 holds I0 for layer 1, then is reused as I1 for layer 2.
__device__ float g_I0[(size_t)MTOT * HH];   // 64 MB
__device__ float g_S1[(size_t)MTOT * HH];   // 64 MB (layer-1 spikes)
__device__ float g_SF[BATCH * HH];          // final layer-2 spikes

// ---------------------------------------------------------------------------
// SGEMM: C[M,N] = A[M,K] * W[N,K]^T + bias[N]
// Classic 128x128x8 tile, 256 threads, 8x8 per-thread microtile, float4 I/O.
// M=32768, N=512, K=512 for both GEMMs (shapes divide evenly; no bounds checks).
// ---------------------------------------------------------------------------
__global__ __launch_bounds__(256, 2) void sgemm_bias(
    const float* __restrict__ A, const float* __restrict__ W,
    const float* __restrict__ bias, float* __restrict__ C,
    int M, int N, int K)
{
    constexpr int BM = 128, BN = 128, BK = 8;
    __shared__ float As[BK][BM];
    __shared__ float Ws[BK][BN];

    const int tid = threadIdx.x;
    const int bm = blockIdx.y * BM;
    const int bn = blockIdx.x * BN;

    // Global load mapping: 2 threads per row, each loads a float4 along K.
    const int lr = tid >> 1;            // 0..127
    const int lc = (tid & 1) << 2;      // 0 or 4
    const float* Ag = A + (size_t)(bm + lr) * K + lc;
    const float* Wg = W + (size_t)(bn + lr) * K + lc;

    // Compute mapping: 16x16 thread grid, each computes 8x8.
    const int tm = (tid >> 4) << 3;     // 0,8,...,120
    const int tn = (tid & 15) << 3;

    float acc[8][8];
#pragma unroll
    for (int i = 0; i < 8; i++)
#pragma unroll
        for (int j = 0; j < 8; j++) acc[i][j] = 0.f;

    for (int k0 = 0; k0 < K; k0 += BK) {
        float4 av = *(const float4*)(Ag + k0);
        float4 wv = *(const float4*)(Wg + k0);
        As[lc + 0][lr] = av.x; As[lc + 1][lr] = av.y;
        As[lc + 2][lr] = av.z; As[lc + 3][lr] = av.w;
        Ws[lc + 0][lr] = wv.x; Ws[lc + 1][lr] = wv.y;
        Ws[lc + 2][lr] = wv.z; Ws[lc + 3][lr] = wv.w;
        __syncthreads();

#pragma unroll
        for (int k = 0; k < BK; k++) {
            float a[8], b[8];
            *(float4*)&a[0] = *(const float4*)&As[k][tm];
            *(float4*)&a[4] = *(const float4*)&As[k][tm + 4];
            *(float4*)&b[0] = *(const float4*)&Ws[k][tn];
            *(float4*)&b[4] = *(const float4*)&Ws[k][tn + 4];
#pragma unroll
            for (int i = 0; i < 8; i++)
#pragma unroll
                for (int j = 0; j < 8; j++)
                    acc[i][j] += a[i] * b[j];
        }
        __syncthreads();
    }

    // Epilogue: add bias, float4 stores.
#pragma unroll
    for (int i = 0; i < 8; i++) {
        float* crow = C + (size_t)(bm + tm + i) * N + bn + tn;
#pragma unroll
        for (int j = 0; j < 8; j += 4) {
            float4 v;
            v.x = acc[i][j + 0] + bias[bn + tn + j + 0];
            v.y = acc[i][j + 1] + bias[bn + tn + j + 1];
            v.z = acc[i][j + 2] + bias[bn + tn + j + 2];
            v.w = acc[i][j + 3] + bias[bn + tn + j + 3];
            *(float4*)(crow + j) = v;
        }
    }
}

// ---------------------------------------------------------------------------
// LIF scan: per (b,h) channel, sequential over T.
//   u' = 0.9*(u - s*1.0) + i_t ; s' = (u' > 1.0) ? 1 : 0
// Unfused arithmetic (__fmul_rn/__fadd_rn) to match reference rounding exactly.
// Loads unrolled x8 for MLP (i(t) independent of the recurrence).
// WRITE_ALL=true: write full spike train [B,T,H]. false: write only final [B,H].
// ---------------------------------------------------------------------------
template <bool WRITE_ALL>
__global__ void lif_kernel(const float* __restrict__ I, float* __restrict__ S)
{
    int idx = blockIdx.x * blockDim.x + threadIdx.x;   // 0 .. B*H-1
    if (idx >= BATCH * HH) return;
    int b = idx / HH;
    int h = idx - b * HH;
    size_t base = (size_t)b * TT * HH + h;

    float u = 0.f, s = 0.f;
    for (int t = 0; t < TT; t += 8) {
        float iv[8];
#pragma unroll
        for (int j = 0; j < 8; j++)
            iv[j] = I[base + (size_t)(t + j) * HH];
#pragma unroll
        for (int j = 0; j < 8; j++) {
            float d = __fadd_rn(u, -s);                       // u - s*THRESH
            u = __fadd_rn(__fmul_rn(0.9f, d), iv[j]);         // 0.9*(u-s) + i
            s = (u > 1.0f) ? 1.0f : 0.0f;                     // heaviside(u-1)
            if (WRITE_ALL) S[base + (size_t)(t + j) * HH] = s;
        }
    }
    if (!WRITE_ALL) S[idx] = s;
}

// ---------------------------------------------------------------------------
// Final FC: out[b,o] = sum_h SF[b,h] * fcW[o,h] + fcb[o]
// One block per batch row; spikes staged in smem; 256 threads = 256 outputs.
// ---------------------------------------------------------------------------
__global__ void final_fc(const float* __restrict__ SF, const float* __restrict__ fcW,
                         const float* __restrict__ fcb, float* __restrict__ out)
{
    __shared__ float ss[HH];
    int b = blockIdx.x;
    for (int h = threadIdx.x; h < HH; h += blockDim.x)
        ss[h] = SF[b * HH + h];
    __syncthreads();

    int o = threadIdx.x;   // 256 threads, 256 outputs
    const float4* wrow = (const float4*)(fcW + (size_t)o * HH);
    float acc = 0.f;
#pragma unroll 4
    for (int h4 = 0; h4 < HH / 4; h4++) {
        float4 w = wrow[h4];
        float4 sv = *(const float4*)&ss[h4 * 4];
        acc += w.x * sv.x + w.y * sv.y + w.z * sv.z + w.w * sv.w;
    }
    out[b * OO + o] = acc + fcb[o];
}

// ---------------------------------------------------------------------------
extern "C" void kernel_launch(void* const* d_in, const int* in_sizes, int n_in,
                              void* d_out, int out_size)
{
    const float* x   = (const float*)d_in[0];
    const float* W0  = (const float*)d_in[1];
    const float* b0  = (const float*)d_in[2];
    const float* W1  = (const float*)d_in[3];
    const float* b1  = (const float*)d_in[4];
    const float* fcW = (const float*)d_in[5];
    const float* fcb = (const float*)d_in[6];
    float* out = (float*)d_out;

    float *I0p, *S1p, *SFp;
    cudaGetSymbolAddress((void**)&I0p, g_I0);
    cudaGetSymbolAddress((void**)&S1p, g_S1);
    cudaGetSymbolAddress((void**)&SFp, g_SF);

    dim3 ggrid(HH / 128, MTOT / 128);   // (4, 256)

    // Layer 1: I0 = x @ W0^T + b0 ; S1 = LIF(I0)
    sgemm_bias<<<ggrid, 256>>>(x, W0, b0, I0p, MTOT, HH, DD);
    lif_kernel<true><<<(BATCH * HH) / 128, 128>>>(I0p, S1p);

    // Layer 2: I1 = S1 @ W1^T + b1 (reuse I0 buffer) ; SF = final LIF spikes
    sgemm_bias<<<ggrid, 256>>>(S1p, W1, b1, I0p, MTOT, HH, HH);
    lif_kernel<false><<<(BATCH * HH) / 128, 128>>>(I0p, SFp);

    // Readout: out = SF @ fcW^T + fcb
    final_fc<<<BATCH, 256>>>(SFp, fcW, fcb, out);
}

// round 3
// speedup vs baseline: 1.2229x; 1.2229x over previous
#include <cuda_runtime.h>
#include <cstdint>

#define BATCH 32
#define TT    1024
#define DD    512
#define HH    512
#define OO    256
#define MTOT  (BATCH * TT)   // 32768

__device__ float g_I0[(size_t)MTOT * HH];   // currents (reused layer1/layer2)
__device__ float g_S1[(size_t)MTOT * HH];   // layer-1 spikes
__device__ float g_SF[BATCH * HH];          // final layer-2 spikes

// ---------------------------------------------------------------------------
// tf32 helpers
// ---------------------------------------------------------------------------
__device__ __forceinline__ uint32_t f2tf(float x) {   // round-to-nearest tf32 bits
    uint32_t u;
    asm("cvt.rna.tf32.f32 %0, %1;" : "=r"(u) : "f"(x));
    return u;
}

__device__ __forceinline__ void mma_tf32(float* d, const uint32_t* a, const uint32_t* b) {
    asm volatile(
        "mma.sync.aligned.m16n8k8.row.col.f32.tf32.tf32.f32 "
        "{%0,%1,%2,%3}, {%4,%5,%6,%7}, {%8,%9}, {%0,%1,%2,%3};"
        : "+f"(d[0]), "+f"(d[1]), "+f"(d[2]), "+f"(d[3])
        : "r"(a[0]), "r"(a[1]), "r"(a[2]), "r"(a[3]), "r"(b[0]), "r"(b[1]));
}

// ---------------------------------------------------------------------------
// Split-precision tf32 GEMM via mma.sync (HMMA), C[M,512] = A[M,K]*W[512,K]^T + b
// Block 128x128, BK=16, 8 warps (2x4), warp tile 64x32.
// smem tiles stored k-major: T[k][m], row pitch 136 floats -> bank = (8k+m)&31,
// conflict-free for all fragment loads.
// SPLIT_A: 4 mma passes (hi/lo x hi/lo). else 2 passes (A exact, B hi/lo).
// ---------------------------------------------------------------------------
template <bool SPLIT_A>
__global__ __launch_bounds__(256, 1) void gemm_mma(
    const float* __restrict__ A, const float* __restrict__ W,
    const float* __restrict__ bias, float* __restrict__ C, int K)
{
    constexpr int ST  = 136;          // smem row pitch (floats)
    constexpr int TSZ = 16 * ST;      // words per 128x16 tile
    constexpr int NT  = SPLIT_A ? 4 : 3;   // tiles per stage: Ahi[,Alo],Bhi,Blo
    extern __shared__ uint32_t sm[];

    const int tid = threadIdx.x;
    const int lid = tid & 31;
    const int wid = tid >> 5;
    const int bm = blockIdx.y * 128, bn = blockIdx.x * 128;

    // warp tile: 2 (m) x 4 (n)
    const int warp_m = (wid >> 2) * 64;
    const int warp_n = (wid & 3) * 32;

    // global load mapping: 2 threads per row, 8 floats each
    const int gr = tid >> 1;            // row within tile (0..127)
    const int gc = (tid & 1) * 8;       // col group (0 or 8)
    const float* Ag = A + (size_t)(bm + gr) * K + gc;
    const float* Wg = W + (size_t)(bn + gr) * K + gc;

    float acc[4][4][4];
#pragma unroll
    for (int i = 0; i < 4; i++)
#pragma unroll
        for (int j = 0; j < 4; j++)
#pragma unroll
            for (int f = 0; f < 4; f++) acc[i][j][f] = 0.f;

    const int NC = K / 16;
    float4 pa0, pa1, pb0, pb1;
    pa0 = *(const float4*)(Ag + 0); pa1 = *(const float4*)(Ag + 4);
    pb0 = *(const float4*)(Wg + 0); pb1 = *(const float4*)(Wg + 4);

    for (int c = 0; c < NC; c++) {
        const int s = c & 1;
        uint32_t* sAhi = sm + s * (NT * TSZ);
        uint32_t* sAlo = sAhi + TSZ;                      // used iff SPLIT_A
        uint32_t* sBhi = sAhi + (SPLIT_A ? 2 : 1) * TSZ;
        uint32_t* sBlo = sAhi + (SPLIT_A ? 3 : 2) * TSZ;

        // ---- store current chunk (convert fp32 -> tf32 hi/lo) ----
        {
            float av[8] = { pa0.x, pa0.y, pa0.z, pa0.w, pa1.x, pa1.y, pa1.z, pa1.w };
            float wv[8] = { pb0.x, pb0.y, pb0.z, pb0.w, pb1.x, pb1.y, pb1.z, pb1.w };
#pragma unroll
            for (int j = 0; j < 8; j++) {
                int k = gc + j;
                uint32_t bh = f2tf(wv[j]);
                sBhi[k * ST + gr] = bh;
                sBlo[k * ST + gr] = f2tf(wv[j] - __uint_as_float(bh));
                if (SPLIT_A) {
                    uint32_t ah = f2tf(av[j]);
                    sAhi[k * ST + gr] = ah;
                    sAlo[k * ST + gr] = f2tf(av[j] - __uint_as_float(ah));
                } else {
                    sAhi[k * ST + gr] = __float_as_uint(av[j]);   // exact (spikes)
                }
            }
        }
        __syncthreads();

        // ---- prefetch next chunk ----
        if (c + 1 < NC) {
            const float* Agn = Ag + (c + 1) * 16;
            const float* Wgn = Wg + (c + 1) * 16;
            pa0 = *(const float4*)(Agn + 0); pa1 = *(const float4*)(Agn + 4);
            pb0 = *(const float4*)(Wgn + 0); pb1 = *(const float4*)(Wgn + 4);
        }

        // ---- compute: two k8 steps ----
#pragma unroll
        for (int ks = 0; ks < 2; ks++) {
            const int kk = ks * 8;
            const int kq = kk + (lid & 3);
            const int mq = lid >> 2;

            uint32_t ah[4][4], al[4][4], bh[4][2], bl[4][2];
#pragma unroll
            for (int i = 0; i < 4; i++) {
                int m = warp_m + i * 16 + mq;
                ah[i][0] = sAhi[kq * ST + m];
                ah[i][1] = sAhi[kq * ST + m + 8];
                ah[i][2] = sAhi[(kq + 4) * ST + m];
                ah[i][3] = sAhi[(kq + 4) * ST + m + 8];
                if (SPLIT_A) {
                    al[i][0] = sAlo[kq * ST + m];
                    al[i][1] = sAlo[kq * ST + m + 8];
                    al[i][2] = sAlo[(kq + 4) * ST + m];
                    al[i][3] = sAlo[(kq + 4) * ST + m + 8];
                }
            }
#pragma unroll
            for (int j = 0; j < 4; j++) {
                int n = warp_n + j * 8 + mq;
                bh[j][0] = sBhi[kq * ST + n];
                bh[j][1] = sBhi[(kq + 4) * ST + n];
                bl[j][0] = sBlo[kq * ST + n];
                bl[j][1] = sBlo[(kq + 4) * ST + n];
            }

            // lo passes first (accumulate small terms early), hi·hi last
#pragma unroll
            for (int i = 0; i < 4; i++)
#pragma unroll
                for (int j = 0; j < 4; j++) mma_tf32(acc[i][j], ah[i], bl[j]);
            if (SPLIT_A) {
#pragma unroll
                for (int i = 0; i < 4; i++)
#pragma unroll
                    for (int j = 0; j < 4; j++) mma_tf32(acc[i][j], al[i], bh[j]);
#pragma unroll
                for (int i = 0; i < 4; i++)
#pragma unroll
                    for (int j = 0; j < 4; j++) mma_tf32(acc[i][j], al[i], bl[j]);
            }
#pragma unroll
            for (int i = 0; i < 4; i++)
#pragma unroll
                for (int j = 0; j < 4; j++) mma_tf32(acc[i][j], ah[i], bh[j]);
        }
        __syncthreads();
    }

    // ---- epilogue: bias + store (float2 per fragment row) ----
#pragma unroll
    for (int i = 0; i < 4; i++) {
        int row0 = bm + warp_m + i * 16 + (lid >> 2);
#pragma unroll
        for (int j = 0; j < 4; j++) {
            int col = bn + warp_n + j * 8 + (lid & 3) * 2;
            float b0 = bias[col], b1 = bias[col + 1];
            float2 v0 = { acc[i][j][0] + b0, acc[i][j][1] + b1 };
            float2 v1 = { acc[i][j][2] + b0, acc[i][j][3] + b1 };
            *(float2*)(C + (size_t)row0 * HH + col) = v0;
            *(float2*)(C + (size_t)(row0 + 8) * HH + col) = v1;
        }
    }
}

// ---------------------------------------------------------------------------
// LIF scan, unroll x32 for MLP. Matches reference rounding exactly.
// ---------------------------------------------------------------------------
template <bool WRITE_ALL>
__global__ __launch_bounds__(256) void lif_kernel(const float* __restrict__ I,
                                                  float* __restrict__ S)
{
    int idx = blockIdx.x * blockDim.x + threadIdx.x;
    int b = idx >> 9, h = idx & 511;
    size_t base = (size_t)b * TT * HH + h;

    float u = 0.f, s = 0.f;
    for (int t = 0; t < TT; t += 32) {
        float iv[32];
#pragma unroll
        for (int j = 0; j < 32; j++)
            iv[j] = __ldcs(&I[base + (size_t)(t + j) * HH]);
#pragma unroll
        for (int j = 0; j < 32; j++) {
            float d = __fadd_rn(u, -s);
            u = __fadd_rn(__fmul_rn(0.9f, d), iv[j]);
            s = (u > 1.0f) ? 1.0f : 0.0f;
            if (WRITE_ALL) S[base + (size_t)(t + j) * HH] = s;
        }
    }
    if (!WRITE_ALL) S[idx] = s;
}

// ---------------------------------------------------------------------------
__global__ void final_fc(const float* __restrict__ SF, const float* __restrict__ fcW,
                         const float* __restrict__ fcb, float* __restrict__ out)
{
    __shared__ float ss[HH];
    int b = blockIdx.x;
    for (int h = threadIdx.x; h < HH; h += blockDim.x)
        ss[h] = SF[b * HH + h];
    __syncthreads();

    int o = threadIdx.x;
    const float4* wrow = (const float4*)(fcW + (size_t)o * HH);
    float acc = 0.f;
#pragma unroll 4
    for (int h4 = 0; h4 < HH / 4; h4++) {
        float4 w = wrow[h4];
        float4 sv = *(const float4*)&ss[h4 * 4];
        acc += w.x * sv.x + w.y * sv.y + w.z * sv.z + w.w * sv.w;
    }
    out[b * OO + o] = acc + fcb[o];
}

// ---------------------------------------------------------------------------
extern "C" void kernel_launch(void* const* d_in, const int* in_sizes, int n_in,
                              void* d_out, int out_size)
{
    const float* x   = (const float*)d_in[0];
    const float* W0  = (const float*)d_in[1];
    const float* b0  = (const float*)d_in[2];
    const float* W1  = (const float*)d_in[3];
    const float* b1  = (const float*)d_in[4];
    const float* fcW = (const float*)d_in[5];
    const float* fcb = (const float*)d_in[6];
    float* out = (float*)d_out;

    float *I0p, *S1p, *SFp;
    cudaGetSymbolAddress((void**)&I0p, g_I0);
    cudaGetSymbolAddress((void**)&S1p, g_S1);
    cudaGetSymbolAddress((void**)&SFp, g_SF);

    const int SMEM1 = 2 * 4 * 16 * 136 * 4;   // 69632 B (split A)
    const int SMEM2 = 2 * 3 * 16 * 136 * 4;   // 52224 B (exact A)
    cudaFuncSetAttribute(gemm_mma<true>,  cudaFuncAttributeMaxDynamicSharedMemorySize, SMEM1);
    cudaFuncSetAttribute(gemm_mma<false>, cudaFuncAttributeMaxDynamicSharedMemorySize, SMEM2);

    dim3 ggrid(HH / 128, MTOT / 128);   // (4, 256)

    gemm_mma<true><<<ggrid, 256, SMEM1>>>(x, W0, b0, I0p, DD);
    lif_kernel<true><<<(BATCH * HH) / 256, 256>>>(I0p, S1p);

    gemm_mma<false><<<ggrid, 256, SMEM2>>>(S1p, W1, b1, I0p, HH);
    lif_kernel<false><<<(BATCH * HH) / 256, 256>>>(I0p, SFp);

    final_fc<<<BATCH, 256>>>(SFp, fcW, fcb, out);
}

// round 4
// speedup vs baseline: 1.8736x; 1.5321x over previous
#include <cuda_runtime.h>
#include <cuda_fp16.h>
#include <cstdint>

#define BATCH 32
#define TT    1024
#define DD    512
#define HH    512
#define OO    256
#define MTOT  (BATCH * TT)   // 32768

__device__ float  g_I0[(size_t)MTOT * HH];   // currents (reused layer1/layer2)
__device__ __half g_S1[(size_t)MTOT * HH];   // layer-1 spikes (fp16, exact 0/1)
__device__ float  g_SF[BATCH * HH];          // final layer-2 spikes

// ---------------------------------------------------------------------------
// fp16 MMA helpers
// ---------------------------------------------------------------------------
__device__ __forceinline__ void mma_f16(float* d, const uint32_t* a, const uint32_t* b) {
    asm volatile(
        "mma.sync.aligned.m16n8k16.row.col.f32.f16.f16.f32 "
        "{%0,%1,%2,%3}, {%4,%5,%6,%7}, {%8,%9}, {%0,%1,%2,%3};"
        : "+f"(d[0]), "+f"(d[1]), "+f"(d[2]), "+f"(d[3])
        : "r"(a[0]), "r"(a[1]), "r"(a[2]), "r"(a[3]), "r"(b[0]), "r"(b[1]));
}
__device__ __forceinline__ uint32_t pack2(__half a, __half b) {
    __half2 h = __halves2half2(a, b);
    return *(uint32_t*)&h;
}

// smem tile: [row 0..127][k 0..15 half], row pitch 12 u32 (8 data + 4 pad)
// bank(u32) = (12*row + kq) % 32 -> conflict-free for all fragment patterns.
#define PITCH 12
#define TSZ   (128 * PITCH)        // u32 words per tile
#define INV2048 4.8828125e-4f

// ---------------------------------------------------------------------------
// GEMM1: C[M,512] = A[M,512] * W[512,512]^T + bias   (A,W fp32)
// fp16 split: a=ah+al, w=wh+wl (lo stored *2048). 3 passes:
//   accH += ah*wh ; accL += ah*wlx + alx*wh ; C = accH + accL/2048 + bias
// Block 128x128, BK=16, 8 warps (2x4), warp tile 64x32, double-buffered.
// ---------------------------------------------------------------------------
__global__ __launch_bounds__(256, 1) void gemm1_f16(
    const float* __restrict__ A, const float* __restrict__ W,
    const float* __restrict__ bias, float* __restrict__ C, int K)
{
    extern __shared__ uint32_t sm[];
    const int tid = threadIdx.x, lid = tid & 31, wid = tid >> 5;
    const int bm = blockIdx.y * 128, bn = blockIdx.x * 128;
    const int warp_m = (wid >> 2) * 64, warp_n = (wid & 3) * 32;

    const int gr = tid >> 1, gq = tid & 1;              // fill: 2 thr/row, 8 vals
    const float* Ag = A + (size_t)(bm + gr) * K + gq * 8;
    const float* Wg = W + (size_t)(bn + gr) * K + gq * 8;

    float accH[4][4][4], accL[4][4][4];
#pragma unroll
    for (int i = 0; i < 4; i++)
#pragma unroll
        for (int j = 0; j < 4; j++)
#pragma unroll
            for (int f = 0; f < 4; f++) { accH[i][j][f] = 0.f; accL[i][j][f] = 0.f; }

    const int NC = K / 16;
    float4 pa0 = *(const float4*)Ag,       pa1 = *(const float4*)(Ag + 4);
    float4 pb0 = *(const float4*)Wg,       pb1 = *(const float4*)(Wg + 4);

    for (int c = 0; c < NC; c++) {
        uint32_t* stg = sm + (c & 1) * (4 * TSZ);
        uint32_t* sAh = stg;
        uint32_t* sAl = stg + TSZ;
        uint32_t* sBh = stg + 2 * TSZ;
        uint32_t* sBl = stg + 3 * TSZ;

        {   // convert fp32 -> (hi, lo*2048) fp16 and store
            float av[8] = { pa0.x, pa0.y, pa0.z, pa0.w, pa1.x, pa1.y, pa1.z, pa1.w };
            float wv[8] = { pb0.x, pb0.y, pb0.z, pb0.w, pb1.x, pb1.y, pb1.z, pb1.w };
            __half ahh[8], alh[8], bhh[8], blh[8];
#pragma unroll
            for (int j = 0; j < 8; j++) {
                ahh[j] = __float2half_rn(av[j]);
                alh[j] = __float2half_rn((av[j] - __half2float(ahh[j])) * 2048.f);
                bhh[j] = __float2half_rn(wv[j]);
                blh[j] = __float2half_rn((wv[j] - __half2float(bhh[j])) * 2048.f);
            }
            uint4 vah = { pack2(ahh[0],ahh[1]), pack2(ahh[2],ahh[3]), pack2(ahh[4],ahh[5]), pack2(ahh[6],ahh[7]) };
            uint4 val = { pack2(alh[0],alh[1]), pack2(alh[2],alh[3]), pack2(alh[4],alh[5]), pack2(alh[6],alh[7]) };
            uint4 vbh = { pack2(bhh[0],bhh[1]), pack2(bhh[2],bhh[3]), pack2(bhh[4],bhh[5]), pack2(bhh[6],bhh[7]) };
            uint4 vbl = { pack2(blh[0],blh[1]), pack2(blh[2],blh[3]), pack2(blh[4],blh[5]), pack2(blh[6],blh[7]) };
            int o = gr * PITCH + gq * 4;
            *(uint4*)(sAh + o) = vah;  *(uint4*)(sAl + o) = val;
            *(uint4*)(sBh + o) = vbh;  *(uint4*)(sBl + o) = vbl;
        }
        __syncthreads();

        if (c + 1 < NC) {
            const float* An = Ag + (c + 1) * 16;
            const float* Wn = Wg + (c + 1) * 16;
            pa0 = *(const float4*)An; pa1 = *(const float4*)(An + 4);
            pb0 = *(const float4*)Wn; pb1 = *(const float4*)(Wn + 4);
        }

        const int mq = lid >> 2, kq = lid & 3;
        uint32_t ah[4][4], al[4][4], bh[4][2], bl[4][2];
#pragma unroll
        for (int i = 0; i < 4; i++) {
            int m = warp_m + i * 16 + mq;
            ah[i][0] = sAh[m * PITCH + kq];           ah[i][1] = sAh[(m + 8) * PITCH + kq];
            ah[i][2] = sAh[m * PITCH + kq + 4];       ah[i][3] = sAh[(m + 8) * PITCH + kq + 4];
            al[i][0] = sAl[m * PITCH + kq];           al[i][1] = sAl[(m + 8) * PITCH + kq];
            al[i][2] = sAl[m * PITCH + kq + 4];       al[i][3] = sAl[(m + 8) * PITCH + kq + 4];
        }
#pragma unroll
        for (int j = 0; j < 4; j++) {
            int n = warp_n + j * 8 + mq;
            bh[j][0] = sBh[n * PITCH + kq];  bh[j][1] = sBh[n * PITCH + kq + 4];
            bl[j][0] = sBl[n * PITCH + kq];  bl[j][1] = sBl[n * PITCH + kq + 4];
        }
#pragma unroll
        for (int i = 0; i < 4; i++)
#pragma unroll
            for (int j = 0; j < 4; j++) {
                mma_f16(accH[i][j], ah[i], bh[j]);
                mma_f16(accL[i][j], ah[i], bl[j]);
                mma_f16(accL[i][j], al[i], bh[j]);
            }
        __syncthreads();
    }

#pragma unroll
    for (int i = 0; i < 4; i++) {
        int row0 = bm + warp_m + i * 16 + (lid >> 2);
#pragma unroll
        for (int j = 0; j < 4; j++) {
            int col = bn + warp_n + j * 8 + (lid & 3) * 2;
            float b0 = bias[col], b1 = bias[col + 1];
            float2 v0 = { accH[i][j][0] + accL[i][j][0] * INV2048 + b0,
                          accH[i][j][1] + accL[i][j][1] * INV2048 + b1 };
            float2 v1 = { accH[i][j][2] + accL[i][j][2] * INV2048 + b0,
                          accH[i][j][3] + accL[i][j][3] * INV2048 + b1 };
            *(float2*)(C + (size_t)row0 * HH + col) = v0;
            *(float2*)(C + (size_t)(row0 + 8) * HH + col) = v1;
        }
    }
}

// ---------------------------------------------------------------------------
// GEMM2: C[M,512] = S[M,512](fp16 exact) * W[512,512]^T + bias
// 2 passes: accH += s*wh ; accL += s*wlx ; C = accH + accL/2048 + bias
// ---------------------------------------------------------------------------
__global__ __launch_bounds__(256, 1) void gemm2_f16(
    const __half* __restrict__ A, const float* __restrict__ W,
    const float* __restrict__ bias, float* __restrict__ C, int K)
{
    extern __shared__ uint32_t sm[];
    const int tid = threadIdx.x, lid = tid & 31, wid = tid >> 5;
    const int bm = blockIdx.y * 128, bn = blockIdx.x * 128;
    const int warp_m = (wid >> 2) * 64, warp_n = (wid & 3) * 32;

    const int gr = tid >> 1, gq = tid & 1;
    const __half* Ag = A + (size_t)(bm + gr) * K + gq * 8;
    const float*  Wg = W + (size_t)(bn + gr) * K + gq * 8;

    float accH[4][4][4], accL[4][4][4];
#pragma unroll
    for (int i = 0; i < 4; i++)
#pragma unroll
        for (int j = 0; j < 4; j++)
#pragma unroll
            for (int f = 0; f < 4; f++) { accH[i][j][f] = 0.f; accL[i][j][f] = 0.f; }

    const int NC = K / 16;
    uint4  paq = *(const uint4*)Ag;                       // 8 half
    float4 pb0 = *(const float4*)Wg, pb1 = *(const float4*)(Wg + 4);

    for (int c = 0; c < NC; c++) {
        uint32_t* stg = sm + (c & 1) * (3 * TSZ);
        uint32_t* sAh = stg;
        uint32_t* sBh = stg + TSZ;
        uint32_t* sBl = stg + 2 * TSZ;

        {
            float wv[8] = { pb0.x, pb0.y, pb0.z, pb0.w, pb1.x, pb1.y, pb1.z, pb1.w };
            __half bhh[8], blh[8];
#pragma unroll
            for (int j = 0; j < 8; j++) {
                bhh[j] = __float2half_rn(wv[j]);
                blh[j] = __float2half_rn((wv[j] - __half2float(bhh[j])) * 2048.f);
            }
            uint4 vbh = { pack2(bhh[0],bhh[1]), pack2(bhh[2],bhh[3]), pack2(bhh[4],bhh[5]), pack2(bhh[6],bhh[7]) };
            uint4 vbl = { pack2(blh[0],blh[1]), pack2(blh[2],blh[3]), pack2(blh[4],blh[5]), pack2(blh[6],blh[7]) };
            int o = gr * PITCH + gq * 4;
            *(uint4*)(sAh + o) = paq;
            *(uint4*)(sBh + o) = vbh;
            *(uint4*)(sBl + o) = vbl;
        }
        __syncthreads();

        if (c + 1 < NC) {
            paq = *(const uint4*)(Ag + (c + 1) * 16);
            const float* Wn = Wg + (c + 1) * 16;
            pb0 = *(const float4*)Wn; pb1 = *(const float4*)(Wn + 4);
        }

        const int mq = lid >> 2, kq = lid & 3;
        uint32_t ah[4][4], bh[4][2], bl[4][2];
#pragma unroll
        for (int i = 0; i < 4; i++) {
            int m = warp_m + i * 16 + mq;
            ah[i][0] = sAh[m * PITCH + kq];      ah[i][1] = sAh[(m + 8) * PITCH + kq];
            ah[i][2] = sAh[m * PITCH + kq + 4];  ah[i][3] = sAh[(m + 8) * PITCH + kq + 4];
        }
#pragma unroll
        for (int j = 0; j < 4; j++) {
            int n = warp_n + j * 8 + mq;
            bh[j][0] = sBh[n * PITCH + kq];  bh[j][1] = sBh[n * PITCH + kq + 4];
            bl[j][0] = sBl[n * PITCH + kq];  bl[j][1] = sBl[n * PITCH + kq + 4];
        }
#pragma unroll
        for (int i = 0; i < 4; i++)
#pragma unroll
            for (int j = 0; j < 4; j++) {
                mma_f16(accH[i][j], ah[i], bh[j]);
                mma_f16(accL[i][j], ah[i], bl[j]);
            }
        __syncthreads();
    }

#pragma unroll
    for (int i = 0; i < 4; i++) {
        int row0 = bm + warp_m + i * 16 + (lid >> 2);
#pragma unroll
        for (int j = 0; j < 4; j++) {
            int col = bn + warp_n + j * 8 + (lid & 3) * 2;
            float b0 = bias[col], b1 = bias[col + 1];
            float2 v0 = { accH[i][j][0] + accL[i][j][0] * INV2048 + b0,
                          accH[i][j][1] + accL[i][j][1] * INV2048 + b1 };
            float2 v1 = { accH[i][j][2] + accL[i][j][2] * INV2048 + b0,
                          accH[i][j][3] + accL[i][j][3] * INV2048 + b1 };
            *(float2*)(C + (size_t)row0 * HH + col) = v0;
            *(float2*)(C + (size_t)(row0 + 8) * HH + col) = v1;
        }
    }
}

// ---------------------------------------------------------------------------
// LIF scans: 2 channels/thread (float2), unroll 32 -> deep MLP.
// Exact reference rounding: u' = rn(rn(0.9*rn(u-s)) + i) ; s' = u'>1.
// ---------------------------------------------------------------------------
__global__ __launch_bounds__(64) void lif_spike_h(const float* __restrict__ I,
                                                  __half* __restrict__ S)
{
    int idx = blockIdx.x * 64 + threadIdx.x;       // 0..8191
    int b = idx >> 8, h = (idx & 255) * 2;
    size_t base = (size_t)b * TT * HH + h;

    float u0 = 0.f, s0 = 0.f, u1 = 0.f, s1 = 0.f;
    for (int t = 0; t < TT; t += 32) {
        float2 iv[32];
#pragma unroll
        for (int j = 0; j < 32; j++)
            iv[j] = *(const float2*)(I + base + (size_t)(t + j) * HH);
#pragma unroll
        for (int j = 0; j < 32; j++) {
            u0 = __fadd_rn(__fmul_rn(0.9f, __fadd_rn(u0, -s0)), iv[j].x);
            s0 = (u0 > 1.0f) ? 1.0f : 0.0f;
            u1 = __fadd_rn(__fmul_rn(0.9f, __fadd_rn(u1, -s1)), iv[j].y);
            s1 = (u1 > 1.0f) ? 1.0f : 0.0f;
            *(__half2*)(S + base + (size_t)(t + j) * HH) = __floats2half2_rn(s0, s1);
        }
    }
}

__global__ __launch_bounds__(64) void lif_last(const float* __restrict__ I,
                                               float* __restrict__ SF)
{
    int idx = blockIdx.x * 64 + threadIdx.x;       // 0..8191
    int b = idx >> 8, h = (idx & 255) * 2;
    size_t base = (size_t)b * TT * HH + h;

    float u0 = 0.f, s0 = 0.f, u1 = 0.f, s1 = 0.f;
    for (int t = 0; t < TT; t += 32) {
        float2 iv[32];
#pragma unroll
        for (int j = 0; j < 32; j++)
            iv[j] = *(const float2*)(I + base + (size_t)(t + j) * HH);
#pragma unroll
        for (int j = 0; j < 32; j++) {
            u0 = __fadd_rn(__fmul_rn(0.9f, __fadd_rn(u0, -s0)), iv[j].x);
            s0 = (u0 > 1.0f) ? 1.0f : 0.0f;
            u1 = __fadd_rn(__fmul_rn(0.9f, __fadd_rn(u1, -s1)), iv[j].y);
            s1 = (u1 > 1.0f) ? 1.0f : 0.0f;
        }
    }
    float2 v = { s0, s1 };
    *(float2*)(SF + b * HH + h) = v;
}

// ---------------------------------------------------------------------------
__global__ void final_fc(const float* __restrict__ SF, const float* __restrict__ fcW,
                         const float* __restrict__ fcb, float* __restrict__ out)
{
    __shared__ float ss[HH];
    int b = blockIdx.x;
    for (int h = threadIdx.x; h < HH; h += blockDim.x)
        ss[h] = SF[b * HH + h];
    __syncthreads();

    int o = threadIdx.x;
    const float4* wrow = (const float4*)(fcW + (size_t)o * HH);
    float acc = 0.f;
#pragma unroll 4
    for (int h4 = 0; h4 < HH / 4; h4++) {
        float4 w = wrow[h4];
        float4 sv = *(const float4*)&ss[h4 * 4];
        acc += w.x * sv.x + w.y * sv.y + w.z * sv.z + w.w * sv.w;
    }
    out[b * OO + o] = acc + fcb[o];
}

// ---------------------------------------------------------------------------
extern "C" void kernel_launch(void* const* d_in, const int* in_sizes, int n_in,
                              void* d_out, int out_size)
{
    const float* x   = (const float*)d_in[0];
    const float* W0  = (const float*)d_in[1];
    const float* b0  = (const float*)d_in[2];
    const float* W1  = (const float*)d_in[3];
    const float* b1  = (const float*)d_in[4];
    const float* fcW = (const float*)d_in[5];
    const float* fcb = (const float*)d_in[6];
    float* out = (float*)d_out;

    float *I0p, *SFp; __half* S1p;
    cudaGetSymbolAddress((void**)&I0p, g_I0);
    cudaGetSymbolAddress((void**)&S1p, g_S1);
    cudaGetSymbolAddress((void**)&SFp, g_SF);

    const int SMEM1 = 2 * 4 * TSZ * 4;   // 49152 B
    const int SMEM2 = 2 * 3 * TSZ * 4;   // 36864 B
    cudaFuncSetAttribute(gemm1_f16, cudaFuncAttributeMaxDynamicSharedMemorySize, SMEM1);
    cudaFuncSetAttribute(gemm2_f16, cudaFuncAttributeMaxDynamicSharedMemorySize, SMEM2);

    dim3 ggrid(HH / 128, MTOT / 128);   // (4, 256)

    gemm1_f16<<<ggrid, 256, SMEM1>>>(x, W0, b0, I0p, DD);
    lif_spike_h<<<128, 64>>>(I0p, S1p);

    gemm2_f16<<<ggrid, 256, SMEM2>>>(S1p, W1, b1, I0p, HH);
    lif_last<<<128, 64>>>(I0p, SFp);

    final_fc<<<BATCH, 256>>>(SFp, fcW, fcb, out);
}

// round 5
// speedup vs baseline: 2.3033x; 1.2293x over previous
#include <cuda_runtime.h>
#include <cuda_fp16.h>
#include <cstdint>

#define BATCH 32
#define TT    1024
#define DD    512
#define HH    512
#define OO    256
#define MTOT  (BATCH * TT)   // 32768

__device__ float  g_I0[(size_t)MTOT * HH];   // currents (reused layer1/layer2)
__device__ __half g_S1[(size_t)MTOT * HH];   // layer-1 spikes (fp16, exact 0/1)
__device__ float  g_SF[BATCH * HH];          // final layer-2 spikes

// ---------------------------------------------------------------------------
// helpers
// ---------------------------------------------------------------------------
__device__ __forceinline__ uint32_t smem_u32(const void* p) {
    uint32_t a;
    asm("{ .reg .u64 t; cvta.to.shared.u64 t, %1; cvt.u32.u64 %0, t; }"
        : "=r"(a) : "l"(p));
    return a;
}
__device__ __forceinline__ void cp_async16(uint32_t dst, const void* src) {
    asm volatile("cp.async.cg.shared.global [%0], [%1], 16;" :: "r"(dst), "l"(src));
}
#define CP_COMMIT()  asm volatile("cp.async.commit_group;" ::: "memory")
#define CP_WAIT(n)   asm volatile("cp.async.wait_group %0;" :: "n"(n) : "memory")

__device__ __forceinline__ void mma_f16(float* d, const uint32_t* a, const uint32_t* b) {
    asm volatile(
        "mma.sync.aligned.m16n8k16.row.col.f32.f16.f16.f32 "
        "{%0,%1,%2,%3}, {%4,%5,%6,%7}, {%8,%9}, {%0,%1,%2,%3};"
        : "+f"(d[0]), "+f"(d[1]), "+f"(d[2]), "+f"(d[3])
        : "r"(a[0]), "r"(a[1]), "r"(a[2]), "r"(a[3]), "r"(b[0]), "r"(b[1]));
}
__device__ __forceinline__ uint32_t pack2(__half a, __half b) {
    __half2 h = __halves2half2(a, b);
    return *(uint32_t*)&h;
}

#define PITCH 12
#define TSZ   (128 * PITCH)
#define INV2048 4.8828125e-4f

// ---------------------------------------------------------------------------
// GEMM1: C = A(fp32) * W(fp32)^T + bias, fp16 3-pass split (lo scaled x2048).
// ---------------------------------------------------------------------------
__global__ __launch_bounds__(256, 1) void gemm1_f16(
    const float* __restrict__ A, const float* __restrict__ W,
    const float* __restrict__ bias, float* __restrict__ C, int K)
{
    extern __shared__ uint32_t sm[];
    const int tid = threadIdx.x, lid = tid & 31, wid = tid >> 5;
    const int bm = blockIdx.y * 128, bn = blockIdx.x * 128;
    const int warp_m = (wid >> 2) * 64, warp_n = (wid & 3) * 32;

    const int gr = tid >> 1, gq = tid & 1;
    const float* Ag = A + (size_t)(bm + gr) * K + gq * 8;
    const float* Wg = W + (size_t)(bn + gr) * K + gq * 8;

    float accH[4][4][4], accL[4][4][4];
#pragma unroll
    for (int i = 0; i < 4; i++)
#pragma unroll
        for (int j = 0; j < 4; j++)
#pragma unroll
            for (int f = 0; f < 4; f++) { accH[i][j][f] = 0.f; accL[i][j][f] = 0.f; }

    const int NC = K / 16;
    float4 pa0 = *(const float4*)Ag, pa1 = *(const float4*)(Ag + 4);
    float4 pb0 = *(const float4*)Wg, pb1 = *(const float4*)(Wg + 4);

    for (int c = 0; c < NC; c++) {
        uint32_t* stg = sm + (c & 1) * (4 * TSZ);
        uint32_t* sAh = stg;
        uint32_t* sAl = stg + TSZ;
        uint32_t* sBh = stg + 2 * TSZ;
        uint32_t* sBl = stg + 3 * TSZ;

        {
            float av[8] = { pa0.x, pa0.y, pa0.z, pa0.w, pa1.x, pa1.y, pa1.z, pa1.w };
            float wv[8] = { pb0.x, pb0.y, pb0.z, pb0.w, pb1.x, pb1.y, pb1.z, pb1.w };
            __half ahh[8], alh[8], bhh[8], blh[8];
#pragma unroll
            for (int j = 0; j < 8; j++) {
                ahh[j] = __float2half_rn(av[j]);
                alh[j] = __float2half_rn((av[j] - __half2float(ahh[j])) * 2048.f);
                bhh[j] = __float2half_rn(wv[j]);
                blh[j] = __float2half_rn((wv[j] - __half2float(bhh[j])) * 2048.f);
            }
            uint4 vah = { pack2(ahh[0],ahh[1]), pack2(ahh[2],ahh[3]), pack2(ahh[4],ahh[5]), pack2(ahh[6],ahh[7]) };
            uint4 val = { pack2(alh[0],alh[1]), pack2(alh[2],alh[3]), pack2(alh[4],alh[5]), pack2(alh[6],alh[7]) };
            uint4 vbh = { pack2(bhh[0],bhh[1]), pack2(bhh[2],bhh[3]), pack2(bhh[4],bhh[5]), pack2(bhh[6],bhh[7]) };
            uint4 vbl = { pack2(blh[0],blh[1]), pack2(blh[2],blh[3]), pack2(blh[4],blh[5]), pack2(blh[6],blh[7]) };
            int o = gr * PITCH + gq * 4;
            *(uint4*)(sAh + o) = vah;  *(uint4*)(sAl + o) = val;
            *(uint4*)(sBh + o) = vbh;  *(uint4*)(sBl + o) = vbl;
        }
        __syncthreads();

        if (c + 1 < NC) {
            const float* An = Ag + (c + 1) * 16;
            const float* Wn = Wg + (c + 1) * 16;
            pa0 = *(const float4*)An; pa1 = *(const float4*)(An + 4);
            pb0 = *(const float4*)Wn; pb1 = *(const float4*)(Wn + 4);
        }

        const int mq = lid >> 2, kq = lid & 3;
        uint32_t ah[4][4], al[4][4], bh[4][2], bl[4][2];
#pragma unroll
        for (int i = 0; i < 4; i++) {
            int m = warp_m + i * 16 + mq;
            ah[i][0] = sAh[m * PITCH + kq];           ah[i][1] = sAh[(m + 8) * PITCH + kq];
            ah[i][2] = sAh[m * PITCH + kq + 4];       ah[i][3] = sAh[(m + 8) * PITCH + kq + 4];
            al[i][0] = sAl[m * PITCH + kq];           al[i][1] = sAl[(m + 8) * PITCH + kq];
            al[i][2] = sAl[m * PITCH + kq + 4];       al[i][3] = sAl[(m + 8) * PITCH + kq + 4];
        }
#pragma unroll
        for (int j = 0; j < 4; j++) {
            int n = warp_n + j * 8 + mq;
            bh[j][0] = sBh[n * PITCH + kq];  bh[j][1] = sBh[n * PITCH + kq + 4];
            bl[j][0] = sBl[n * PITCH + kq];  bl[j][1] = sBl[n * PITCH + kq + 4];
        }
#pragma unroll
        for (int i = 0; i < 4; i++)
#pragma unroll
            for (int j = 0; j < 4; j++) {
                mma_f16(accH[i][j], ah[i], bh[j]);
                mma_f16(accL[i][j], ah[i], bl[j]);
                mma_f16(accL[i][j], al[i], bh[j]);
            }
        __syncthreads();
    }

#pragma unroll
    for (int i = 0; i < 4; i++) {
        int row0 = bm + warp_m + i * 16 + (lid >> 2);
#pragma unroll
        for (int j = 0; j < 4; j++) {
            int col = bn + warp_n + j * 8 + (lid & 3) * 2;
            float b0 = bias[col], b1 = bias[col + 1];
            float2 v0 = { accH[i][j][0] + accL[i][j][0] * INV2048 + b0,
                          accH[i][j][1] + accL[i][j][1] * INV2048 + b1 };
            float2 v1 = { accH[i][j][2] + accL[i][j][2] * INV2048 + b0,
                          accH[i][j][3] + accL[i][j][3] * INV2048 + b1 };
            *(float2*)(C + (size_t)row0 * HH + col) = v0;
            *(float2*)(C + (size_t)(row0 + 8) * HH + col) = v1;
        }
    }
}

// ---------------------------------------------------------------------------
// GEMM2: C = S(fp16 exact) * W(fp32)^T + bias, 2-pass.
// ---------------------------------------------------------------------------
__global__ __launch_bounds__(256, 1) void gemm2_f16(
    const __half* __restrict__ A, const float* __restrict__ W,
    const float* __restrict__ bias, float* __restrict__ C, int K)
{
    extern __shared__ uint32_t sm[];
    const int tid = threadIdx.x, lid = tid & 31, wid = tid >> 5;
    const int bm = blockIdx.y * 128, bn = blockIdx.x * 128;
    const int warp_m = (wid >> 2) * 64, warp_n = (wid & 3) * 32;

    const int gr = tid >> 1, gq = tid & 1;
    const __half* Ag = A + (size_t)(bm + gr) * K + gq * 8;
    const float*  Wg = W + (size_t)(bn + gr) * K + gq * 8;

    float accH[4][4][4], accL[4][4][4];
#pragma unroll
    for (int i = 0; i < 4; i++)
#pragma unroll
        for (int j = 0; j < 4; j++)
#pragma unroll
            for (int f = 0; f < 4; f++) { accH[i][j][f] = 0.f; accL[i][j][f] = 0.f; }

    const int NC = K / 16;
    uint4  paq = *(const uint4*)Ag;
    float4 pb0 = *(const float4*)Wg, pb1 = *(const float4*)(Wg + 4);

    for (int c = 0; c < NC; c++) {
        uint32_t* stg = sm + (c & 1) * (3 * TSZ);
        uint32_t* sAh = stg;
        uint32_t* sBh = stg + TSZ;
        uint32_t* sBl = stg + 2 * TSZ;

        {
            float wv[8] = { pb0.x, pb0.y, pb0.z, pb0.w, pb1.x, pb1.y, pb1.z, pb1.w };
            __half bhh[8], blh[8];
#pragma unroll
            for (int j = 0; j < 8; j++) {
                bhh[j] = __float2half_rn(wv[j]);
                blh[j] = __float2half_rn((wv[j] - __half2float(bhh[j])) * 2048.f);
            }
            uint4 vbh = { pack2(bhh[0],bhh[1]), pack2(bhh[2],bhh[3]), pack2(bhh[4],bhh[5]), pack2(bhh[6],bhh[7]) };
            uint4 vbl = { pack2(blh[0],blh[1]), pack2(blh[2],blh[3]), pack2(blh[4],blh[5]), pack2(blh[6],blh[7]) };
            int o = gr * PITCH + gq * 4;
            *(uint4*)(sAh + o) = paq;
            *(uint4*)(sBh + o) = vbh;
            *(uint4*)(sBl + o) = vbl;
        }
        __syncthreads();

        if (c + 1 < NC) {
            paq = *(const uint4*)(Ag + (c + 1) * 16);
            const float* Wn = Wg + (c + 1) * 16;
            pb0 = *(const float4*)Wn; pb1 = *(const float4*)(Wn + 4);
        }

        const int mq = lid >> 2, kq = lid & 3;
        uint32_t ah[4][4], bh[4][2], bl[4][2];
#pragma unroll
        for (int i = 0; i < 4; i++) {
            int m = warp_m + i * 16 + mq;
            ah[i][0] = sAh[m * PITCH + kq];      ah[i][1] = sAh[(m + 8) * PITCH + kq];
            ah[i][2] = sAh[m * PITCH + kq + 4];  ah[i][3] = sAh[(m + 8) * PITCH + kq + 4];
        }
#pragma unroll
        for (int j = 0; j < 4; j++) {
            int n = warp_n + j * 8 + mq;
            bh[j][0] = sBh[n * PITCH + kq];  bh[j][1] = sBh[n * PITCH + kq + 4];
            bl[j][0] = sBl[n * PITCH + kq];  bl[j][1] = sBl[n * PITCH + kq + 4];
        }
#pragma unroll
        for (int i = 0; i < 4; i++)
#pragma unroll
            for (int j = 0; j < 4; j++) {
                mma_f16(accH[i][j], ah[i], bh[j]);
                mma_f16(accL[i][j], ah[i], bl[j]);
            }
        __syncthreads();
    }

#pragma unroll
    for (int i = 0; i < 4; i++) {
        int row0 = bm + warp_m + i * 16 + (lid >> 2);
#pragma unroll
        for (int j = 0; j < 4; j++) {
            int col = bn + warp_n + j * 8 + (lid & 3) * 2;
            float b0 = bias[col], b1 = bias[col + 1];
            float2 v0 = { accH[i][j][0] + accL[i][j][0] * INV2048 + b0,
                          accH[i][j][1] + accL[i][j][1] * INV2048 + b1 };
            float2 v1 = { accH[i][j][2] + accL[i][j][2] * INV2048 + b0,
                          accH[i][j][3] + accL[i][j][3] * INV2048 + b1 };
            *(float2*)(C + (size_t)row0 * HH + col) = v0;
            *(float2*)(C + (size_t)(row0 + 8) * HH + col) = v1;
        }
    }
}

// ---------------------------------------------------------------------------
// LIF scan with cp.async smem pipeline.
// Block = 128 threads = 128 channels (one batch b, one 128-wide h tile).
// Grid = 128. 3-stage ring of [64 t x 128 h] fp32 tiles (32KB each).
// Exact reference rounding: u' = rn(rn(0.9*rn(u-s)) + i); s' = u' > 1.
// ---------------------------------------------------------------------------
template <bool WRITE_ALL>
__global__ __launch_bounds__(128) void lif_scan(const float* __restrict__ I,
                                                __half* __restrict__ S,
                                                float* __restrict__ SF)
{
    extern __shared__ float buf[];                 // 3 * 64 * 128 floats
    const int tid = threadIdx.x;
    const int b  = blockIdx.x >> 2;
    const int h0 = (blockIdx.x & 3) * 128;
    const float* src = I + (size_t)b * TT * HH + h0;
    __half* sdst = WRITE_ALL ? (S + (size_t)b * TT * HH + h0 + tid) : nullptr;

    const uint32_t sb = smem_u32(buf);
    constexpr int STAGE_W = 64 * 128;              // floats per stage

    // issue one stage's loads: 16 x 16B per thread, fully independent
    auto load_stage = [&](int st) {
        const float* g = src + (size_t)st * 64 * HH;
        uint32_t d = sb + (uint32_t)(st % 3) * STAGE_W * 4;
#pragma unroll
        for (int s = 0; s < 16; s++) {
            int c = tid + s * 128;                 // 0..2047
            int t = c >> 5, off = (c & 31) * 4;
            cp_async16(d + (uint32_t)(t * 128 + off) * 4, g + (size_t)t * HH + off);
        }
        CP_COMMIT();
    };

    load_stage(0); load_stage(1); load_stage(2);

    float u = 0.f, s = 0.f;
    for (int st = 0; st < 16; st++) {
        CP_WAIT(2);                                // stage st complete
        __syncthreads();
        const float* stage = buf + (st % 3) * STAGE_W;
#pragma unroll
        for (int t = 0; t < 64; t++) {
            float iv = stage[t * 128 + tid];
            u = __fadd_rn(__fmul_rn(0.9f, __fadd_rn(u, -s)), iv);
            s = (u > 1.0f) ? 1.0f : 0.0f;
            if (WRITE_ALL)
                sdst[(size_t)(st * 64 + t) * HH] = __float2half_rn(s);
        }
        __syncthreads();                           // everyone done with buf[st%3]
        if (st + 3 < 16) load_stage(st + 3);
    }
    if (!WRITE_ALL) SF[b * HH + h0 + tid] = s;
}

// ---------------------------------------------------------------------------
__global__ void final_fc(const float* __restrict__ SF, const float* __restrict__ fcW,
                         const float* __restrict__ fcb, float* __restrict__ out)
{
    __shared__ float ss[HH];
    int b = blockIdx.x;
    for (int h = threadIdx.x; h < HH; h += blockDim.x)
        ss[h] = SF[b * HH + h];
    __syncthreads();

    int o = threadIdx.x;
    const float4* wrow = (const float4*)(fcW + (size_t)o * HH);
    float acc = 0.f;
#pragma unroll 4
    for (int h4 = 0; h4 < HH / 4; h4++) {
        float4 w = wrow[h4];
        float4 sv = *(const float4*)&ss[h4 * 4];
        acc += w.x * sv.x + w.y * sv.y + w.z * sv.z + w.w * sv.w;
    }
    out[b * OO + o] = acc + fcb[o];
}

// ---------------------------------------------------------------------------
extern "C" void kernel_launch(void* const* d_in, const int* in_sizes, int n_in,
                              void* d_out, int out_size)
{
    const float* x   = (const float*)d_in[0];
    const float* W0  = (const float*)d_in[1];
    const float* b0  = (const float*)d_in[2];
    const float* W1  = (const float*)d_in[3];
    const float* b1  = (const float*)d_in[4];
    const float* fcW = (const float*)d_in[5];
    const float* fcb = (const float*)d_in[6];
    float* out = (float*)d_out;

    float *I0p, *SFp; __half* S1p;
    cudaGetSymbolAddress((void**)&I0p, g_I0);
    cudaGetSymbolAddress((void**)&S1p, g_S1);
    cudaGetSymbolAddress((void**)&SFp, g_SF);

    const int SMEM1 = 2 * 4 * TSZ * 4;   // 49152 B
    const int SMEM2 = 2 * 3 * TSZ * 4;   // 36864 B
    const int SMEML = 3 * 64 * 128 * 4;  // 98304 B
    cudaFuncSetAttribute(gemm1_f16, cudaFuncAttributeMaxDynamicSharedMemorySize, SMEM1);
    cudaFuncSetAttribute(gemm2_f16, cudaFuncAttributeMaxDynamicSharedMemorySize, SMEM2);
    cudaFuncSetAttribute(lif_scan<true>,  cudaFuncAttributeMaxDynamicSharedMemorySize, SMEML);
    cudaFuncSetAttribute(lif_scan<false>, cudaFuncAttributeMaxDynamicSharedMemorySize, SMEML);

    dim3 ggrid(HH / 128, MTOT / 128);   // (4, 256)

    gemm1_f16<<<ggrid, 256, SMEM1>>>(x, W0, b0, I0p, DD);
    lif_scan<true><<<128, 128, SMEML>>>(I0p, S1p, nullptr);

    gemm2_f16<<<ggrid, 256, SMEM2>>>(S1p, W1, b1, I0p, HH);
    lif_scan<false><<<128, 128, SMEML>>>(I0p, nullptr, SFp);

    final_fc<<<BATCH, 256>>>(SFp, fcW, fcb, out);
}

// round 6
// speedup vs baseline: 2.7783x; 1.2062x over previous
#include <cuda_runtime.h>
#include <cuda_fp16.h>
#include <cstdint>

#define BATCH 32
#define TT    1024
#define DD    512
#define HH    512
#define OO    256
#define MTOT  (BATCH * TT)   // 32768

__device__ float  g_I0[(size_t)MTOT * HH];   // currents (reused layer1/layer2)
__device__ __half g_S1[(size_t)MTOT * HH];   // layer-1 spikes (fp16 exact 0/1)
__device__ float  g_SF[BATCH * HH];          // final layer-2 spikes
__device__ __half g_xh[(size_t)MTOT * DD];   // x hi (fp16)
__device__ __half g_xl[(size_t)MTOT * DD];   // x lo * 2048 (fp16)
__device__ __half g_w0h[HH * DD], g_w0l[HH * DD];
__device__ __half g_w1h[HH * HH], g_w1l[HH * HH];

#define INV2048 4.8828125e-4f
#define PH 40                      // smem row pitch in halves (80B: 16B-aligned, conflict-free)

// ---------------------------------------------------------------------------
// helpers
// ---------------------------------------------------------------------------
__device__ __forceinline__ uint32_t smem_u32(const void* p) {
    uint32_t a;
    asm("{ .reg .u64 t; cvta.to.shared.u64 t, %1; cvt.u32.u64 %0, t; }"
        : "=r"(a) : "l"(p));
    return a;
}
__device__ __forceinline__ void cp_async16(uint32_t dst, const void* src) {
    asm volatile("cp.async.cg.shared.global [%0], [%1], 16;" :: "r"(dst), "l"(src));
}
#define CP_COMMIT()  asm volatile("cp.async.commit_group;" ::: "memory")
#define CP_WAIT(n)   asm volatile("cp.async.wait_group %0;" :: "n"(n) : "memory")

__device__ __forceinline__ void mma_f16(float* d, const uint32_t* a, const uint32_t* b) {
    asm volatile(
        "mma.sync.aligned.m16n8k16.row.col.f32.f16.f16.f32 "
        "{%0,%1,%2,%3}, {%4,%5,%6,%7}, {%8,%9}, {%0,%1,%2,%3};"
        : "+f"(d[0]), "+f"(d[1]), "+f"(d[2]), "+f"(d[3])
        : "r"(a[0]), "r"(a[1]), "r"(a[2]), "r"(a[3]), "r"(b[0]), "r"(b[1]));
}
#define LDSM_X4(r0, r1, r2, r3, addr) \
    asm volatile("ldmatrix.sync.aligned.m8n8.x4.shared.b16 {%0,%1,%2,%3}, [%4];" \
                 : "=r"(r0), "=r"(r1), "=r"(r2), "=r"(r3) : "r"(addr))

// ---------------------------------------------------------------------------
// Split fp32 -> (hi fp16, lo*2048 fp16). n multiple of 1024.
// ---------------------------------------------------------------------------
__global__ __launch_bounds__(256) void conv_split(const float* __restrict__ X,
                                                  __half* __restrict__ Xh,
                                                  __half* __restrict__ Xl)
{
    int i = (blockIdx.x * 256 + threadIdx.x) * 4;
    float4 v = *(const float4*)(X + i);
    __half h0 = __float2half_rn(v.x), h1 = __float2half_rn(v.y);
    __half h2 = __float2half_rn(v.z), h3 = __float2half_rn(v.w);
    __half l0 = __float2half_rn((v.x - __half2float(h0)) * 2048.f);
    __half l1 = __float2half_rn((v.y - __half2float(h1)) * 2048.f);
    __half l2 = __float2half_rn((v.z - __half2float(h2)) * 2048.f);
    __half l3 = __float2half_rn((v.w - __half2float(h3)) * 2048.f);
    __half2 hv0 = __halves2half2(h0, h1), hv1 = __halves2half2(h2, h3);
    __half2 lv0 = __halves2half2(l0, l1), lv1 = __halves2half2(l2, l3);
    uint2 ho = { *(uint32_t*)&hv0, *(uint32_t*)&hv1 };
    uint2 lo = { *(uint32_t*)&lv0, *(uint32_t*)&lv1 };
    *(uint2*)(Xh + i) = ho;
    *(uint2*)(Xl + i) = lo;
}

// ---------------------------------------------------------------------------
// fp16 GEMM: C[M,512] = A*W^T + bias, dual fp32 accumulators (H + L/2048).
// SPLIT_A: passes ah*bh, ah*bl, al*bh. else: ah*bh, ah*bl (A exact).
// Block 128x128, BK=32, 8 warps (2x4), 3-stage cp.async, ldmatrix fragments.
// ---------------------------------------------------------------------------
template <bool SPLIT_A>
__global__ __launch_bounds__(256, 1) void gemm_f16(
    const __half* __restrict__ Ahg, const __half* __restrict__ Alg,
    const __half* __restrict__ Bhg, const __half* __restrict__ Blg,
    const float* __restrict__ bias, float* __restrict__ C, int K)
{
    constexpr int NT     = SPLIT_A ? 4 : 3;
    constexpr int TILE_H = 128 * PH;           // halves per tile
    constexpr int STG_H  = NT * TILE_H;        // halves per stage
    extern __shared__ __half sh[];
    const uint32_t sb = smem_u32(sh);

    const int tid = threadIdx.x, lid = tid & 31, wid = tid >> 5;
    const int bm = blockIdx.y * 128, bn = blockIdx.x * 128;
    const int warp_m = (wid >> 2) * 64, warp_n = (wid & 3) * 32;

    float accH[4][4][4], accL[4][4][4];
#pragma unroll
    for (int i = 0; i < 4; i++)
#pragma unroll
        for (int j = 0; j < 4; j++)
#pragma unroll
            for (int f = 0; f < 4; f++) { accH[i][j][f] = 0.f; accL[i][j][f] = 0.f; }

    const int NC = K / 32;
    const int lr  = tid >> 2;                  // 0..63
    const int loff = (tid & 3) * 8;            // 0,8,16,24

    auto ld_tile = [&](const __half* G, int grow, int kc, uint32_t dst) {
        cp_async16(dst + (uint32_t)(lr * PH + loff) * 2,
                   G + (size_t)(grow + lr) * K + kc + loff);
        cp_async16(dst + (uint32_t)((lr + 64) * PH + loff) * 2,
                   G + (size_t)(grow + lr + 64) * K + kc + loff);
    };
    auto load_stage = [&](int c) {
        const int kc = c * 32;
        uint32_t base = sb + (uint32_t)(c % 3) * STG_H * 2;
        ld_tile(Ahg, bm, kc, base);
        if (SPLIT_A) ld_tile(Alg, bm, kc, base + TILE_H * 2);
        ld_tile(Bhg, bn, kc, base + (SPLIT_A ? 2 : 1) * TILE_H * 2);
        ld_tile(Blg, bn, kc, base + (SPLIT_A ? 3 : 2) * TILE_H * 2);
        CP_COMMIT();
    };

    load_stage(0); load_stage(1); load_stage(2);

    for (int c = 0; c < NC; c++) {
        CP_WAIT(2);
        __syncthreads();
        uint32_t base = sb + (uint32_t)(c % 3) * STG_H * 2;
        uint32_t aH = base;
        uint32_t aL = base + TILE_H * 2;
        uint32_t bH = base + (SPLIT_A ? 2 : 1) * TILE_H * 2;
        uint32_t bL = base + (SPLIT_A ? 3 : 2) * TILE_H * 2;

#pragma unroll
        for (int ks = 0; ks < 2; ks++) {
            const int kb = ks * 16;
            uint32_t ah[4][4], al[4][4], bh[4][2], bl[4][2];

            // A fragments: lanes 0-15 rows m0-15 (k lo), 16-31 same rows (k hi)
            uint32_t arow = ((uint32_t)(warp_m + (lid & 15)) * PH + kb + ((lid >> 4) << 3)) * 2;
#pragma unroll
            for (int i = 0; i < 4; i++) {
                uint32_t off = arow + (uint32_t)i * 16 * PH * 2;
                LDSM_X4(ah[i][0], ah[i][1], ah[i][2], ah[i][3], aH + off);
                if (SPLIT_A) LDSM_X4(al[i][0], al[i][1], al[i][2], al[i][3], aL + off);
            }
            // B fragments: 2 j-tiles per ldmatrix.x4
            uint32_t brow = ((uint32_t)(warp_n + ((lid >> 4) << 3) + (lid & 7)) * PH
                             + kb + (((lid >> 3) & 1) << 3)) * 2;
#pragma unroll
            for (int jp = 0; jp < 2; jp++) {
                uint32_t off = brow + (uint32_t)jp * 16 * PH * 2;
                LDSM_X4(bh[2*jp][0], bh[2*jp][1], bh[2*jp+1][0], bh[2*jp+1][1], bH + off);
                LDSM_X4(bl[2*jp][0], bl[2*jp][1], bl[2*jp+1][0], bl[2*jp+1][1], bL + off);
            }
#pragma unroll
            for (int i = 0; i < 4; i++)
#pragma unroll
                for (int j = 0; j < 4; j++) {
                    mma_f16(accH[i][j], ah[i], bh[j]);
                    mma_f16(accL[i][j], ah[i], bl[j]);
                    if (SPLIT_A) mma_f16(accL[i][j], al[i], bh[j]);
                }
        }
        __syncthreads();
        if (c + 3 < NC) load_stage(c + 3);
    }

#pragma unroll
    for (int i = 0; i < 4; i++) {
        int row0 = bm + warp_m + i * 16 + (lid >> 2);
#pragma unroll
        for (int j = 0; j < 4; j++) {
            int col = bn + warp_n + j * 8 + (lid & 3) * 2;
            float b0 = bias[col], b1 = bias[col + 1];
            float2 v0 = { accH[i][j][0] + accL[i][j][0] * INV2048 + b0,
                          accH[i][j][1] + accL[i][j][1] * INV2048 + b1 };
            float2 v1 = { accH[i][j][2] + accL[i][j][2] * INV2048 + b0,
                          accH[i][j][3] + accL[i][j][3] * INV2048 + b1 };
            *(float2*)(C + (size_t)row0 * HH + col) = v0;
            *(float2*)(C + (size_t)(row0 + 8) * HH + col) = v1;
        }
    }
}

// ---------------------------------------------------------------------------
// LIF scan with 4-stage cp.async smem pipeline. 128 channels per block.
// Exact reference rounding: u' = rn(rn(0.9*rn(u-s)) + i); s' = u' > 1.
// ---------------------------------------------------------------------------
template <bool WRITE_ALL>
__global__ __launch_bounds__(128) void lif_scan(const float* __restrict__ I,
                                                __half* __restrict__ S,
                                                float* __restrict__ SF)
{
    extern __shared__ float buf[];                 // 4 * 64 * 128 floats
    const int tid = threadIdx.x;
    const int b  = blockIdx.x >> 2;
    const int h0 = (blockIdx.x & 3) * 128;
    const float* src = I + (size_t)b * TT * HH + h0;
    __half* sdst = WRITE_ALL ? (S + (size_t)b * TT * HH + h0 + tid) : nullptr;

    const uint32_t sb = smem_u32(buf);
    constexpr int STAGE_W = 64 * 128;

    auto load_stage = [&](int st) {
        const float* g = src + (size_t)st * 64 * HH;
        uint32_t d = sb + (uint32_t)(st & 3) * STAGE_W * 4;
#pragma unroll
        for (int s = 0; s < 16; s++) {
            int c = tid + s * 128;
            int t = c >> 5, off = (c & 31) * 4;
            cp_async16(d + (uint32_t)(t * 128 + off) * 4, g + (size_t)t * HH + off);
        }
        CP_COMMIT();
    };

    load_stage(0); load_stage(1); load_stage(2); load_stage(3);

    float u = 0.f, s = 0.f;
    for (int st = 0; st < 16; st++) {
        CP_WAIT(3);
        __syncthreads();
        const float* stage = buf + (st & 3) * STAGE_W;
#pragma unroll
        for (int t = 0; t < 64; t++) {
            float iv = stage[t * 128 + tid];
            u = __fadd_rn(__fmul_rn(0.9f, __fadd_rn(u, -s)), iv);
            s = (u > 1.0f) ? 1.0f : 0.0f;
            if (WRITE_ALL)
                sdst[(size_t)(st * 64 + t) * HH] = __float2half_rn(s);
        }
        __syncthreads();
        if (st + 4 < 16) load_stage(st + 4);
    }
    if (!WRITE_ALL) SF[b * HH + h0 + tid] = s;
}

// ---------------------------------------------------------------------------
__global__ void final_fc(const float* __restrict__ SF, const float* __restrict__ fcW,
                         const float* __restrict__ fcb, float* __restrict__ out)
{
    __shared__ float ss[HH];
    int b = blockIdx.x;
    for (int h = threadIdx.x; h < HH; h += blockDim.x)
        ss[h] = SF[b * HH + h];
    __syncthreads();

    int o = threadIdx.x;
    const float4* wrow = (const float4*)(fcW + (size_t)o * HH);
    float acc = 0.f;
#pragma unroll 4
    for (int h4 = 0; h4 < HH / 4; h4++) {
        float4 w = wrow[h4];
        float4 sv = *(const float4*)&ss[h4 * 4];
        acc += w.x * sv.x + w.y * sv.y + w.z * sv.z + w.w * sv.w;
    }
    out[b * OO + o] = acc + fcb[o];
}

// ---------------------------------------------------------------------------
extern "C" void kernel_launch(void* const* d_in, const int* in_sizes, int n_in,
                              void* d_out, int out_size)
{
    const float* x   = (const float*)d_in[0];
    const float* W0  = (const float*)d_in[1];
    const float* b0  = (const float*)d_in[2];
    const float* W1  = (const float*)d_in[3];
    const float* b1  = (const float*)d_in[4];
    const float* fcW = (const float*)d_in[5];
    const float* fcb = (const float*)d_in[6];
    float* out = (float*)d_out;

    float *I0p, *SFp; __half *S1p, *xh, *xl, *w0h, *w0l, *w1h, *w1l;
    cudaGetSymbolAddress((void**)&I0p, g_I0);
    cudaGetSymbolAddress((void**)&S1p, g_S1);
    cudaGetSymbolAddress((void**)&SFp, g_SF);
    cudaGetSymbolAddress((void**)&xh,  g_xh);
    cudaGetSymbolAddress((void**)&xl,  g_xl);
    cudaGetSymbolAddress((void**)&w0h, g_w0h);
    cudaGetSymbolAddress((void**)&w0l, g_w0l);
    cudaGetSymbolAddress((void**)&w1h, g_w1h);
    cudaGetSymbolAddress((void**)&w1l, g_w1l);

    const int SMEM1 = 3 * 4 * 128 * PH * 2;   // 122880 B (split A: 4 tiles/stage)
    const int SMEM2 = 3 * 3 * 128 * PH * 2;   //  92160 B
    const int SMEML = 4 * 64 * 128 * 4;       // 131072 B
    cudaFuncSetAttribute(gemm_f16<true>,  cudaFuncAttributeMaxDynamicSharedMemorySize, SMEM1);
    cudaFuncSetAttribute(gemm_f16<false>, cudaFuncAttributeMaxDynamicSharedMemorySize, SMEM2);
    cudaFuncSetAttribute(lif_scan<true>,  cudaFuncAttributeMaxDynamicSharedMemorySize, SMEML);
    cudaFuncSetAttribute(lif_scan<false>, cudaFuncAttributeMaxDynamicSharedMemorySize, SMEML);

    // Pre-split inputs/weights to fp16 hi/lo
    conv_split<<<(MTOT * DD) / 1024, 256>>>(x,  xh,  xl);
    conv_split<<<(HH * DD) / 1024,   256>>>(W0, w0h, w0l);
    conv_split<<<(HH * HH) / 1024,   256>>>(W1, w1h, w1l);

    dim3 ggrid(HH / 128, MTOT / 128);   // (4, 256)

    gemm_f16<true><<<ggrid, 256, SMEM1>>>(xh, xl, w0h, w0l, b0, I0p, DD);
    lif_scan<true><<<128, 128, SMEML>>>(I0p, S1p, nullptr);

    gemm_f16<false><<<ggrid, 256, SMEM2>>>(S1p, nullptr, w1h, w1l, b1, I0p, HH);
    lif_scan<false><<<128, 128, SMEML>>>(I0p, nullptr, SFp);

    final_fc<<<BATCH, 256>>>(SFp, fcW, fcb, out);
}